// round 15
// baseline (speedup 1.0000x reference)
#include <cuda_runtime.h>
#include <cuda_bf16.h>
#include <math.h>
#include <stdint.h>

#define NN   4096
#define EE   131072
#define INF_ 3000
#define HH   4
#define C1   128
#define D1   512   // H*C1
#define LATD 16
#define D2   64    // H*LATD
#define ETOT (EE + NN)
#define NCHC 128   // C1 scan chunks
#define CHLC 32    // C1 chunk length
#define NCHL 256   // LATD scan chunks
#define CHLL 16    // LATD chunk length
#define KP   3008  // padded K for MMA (94*32)
#define KST  32    // K per pipeline stage
#define NSTG (KP / KST)
#define ROWP 40    // padded smem row length in bf16 (32 + 8)
#define TILE_B (128 * ROWP * 2)
#define STG_B  (4 * TILE_B)
#define NPIPE 5    // pipeline stages
#define NSLOT 8    // sort slots (2 halves x 4 heads)
#define SORT_SMEM_U32 (4 * 4096 + 32 * 257)
#define SORT_SMEM_B   (SORT_SMEM_U32 * 4)

// ---------------- scratch (static device globals; no allocation) ----------------
__device__ float g_h1[NN * D1];
__device__ float g_x1[NN * D1];
__device__ float g_x2[NN * D1];
__device__ float g_hs2a[NN * 128];
__device__ float g_hs2b[NN * 128];
__device__ float g_Wc[D1 * 128];
__device__ float g_Wa[INF_ * 8];
__device__ float g_es1[NN * HH];
__device__ float g_ed1[NN * HH];
__device__ float g_es2am[NN * HH];
__device__ float g_ed2am[NN * HH];
__device__ float g_es2as[NN * HH];
__device__ float g_ed2as[NN * HH];
__device__ float g_es2bm[NN * HH];
__device__ float g_ed2bm[NN * HH];
__device__ float g_es2bs[NN * HH];
__device__ float g_ed2bs[NN * HH];
__device__ int   g_off[NN + 1];
__device__ int   g_cur[NN];
__device__ int   g_srcs[ETOT];
__device__ float g_skey[NSLOT * NN];
__device__ int   g_perm[NSLOT * NN];
__device__ float g_w1s[NSLOT * NN];
__device__ float g_w2s[NSLOT * NN];
__device__ float g_Mb[NSLOT];
__device__ float g_s1[NSLOT * (NN + 1)];
__device__ float g_s2[NSLOT * (NN + 1)];
__device__ float g_P1[HH * (NN + 1) * C1];
__device__ float g_S2[HH * (NN + 1) * C1];
__device__ float g_T1[65536];
__device__ float g_T2[65536];
// bf16 hi/lo split operands for HMMA GEMM
__device__ __align__(256) __nv_bfloat16 g_Ahi[(long)NN * KP];
__device__ __align__(256) __nv_bfloat16 g_Alo[(long)NN * KP];
__device__ __align__(256) __nv_bfloat16 g_Bhi[(long)D1 * KP];
__device__ __align__(256) __nv_bfloat16 g_Blo[(long)D1 * KP];

__device__ __forceinline__ float lrelu(float v) { return v > 0.f ? v : 0.2f * v; }

// ---------------- PTX helpers ----------------
__device__ __forceinline__ uint32_t smem_u32(const void* p) {
    return (uint32_t)__cvta_generic_to_shared(p);
}
__device__ __forceinline__ void cp16(uint32_t s, const void* g) {
    asm volatile("cp.async.cg.shared.global [%0], [%1], 16;\n" :: "r"(s), "l"(g));
}
__device__ __forceinline__ void cp_commit() {
    asm volatile("cp.async.commit_group;\n" ::: "memory");
}
template <int W>
__device__ __forceinline__ void cp_wait() {
    asm volatile("cp.async.wait_group %0;\n" :: "n"(W) : "memory");
}

__device__ __forceinline__ void mma_bf16(float& d0, float& d1, float& d2, float& d3,
                                         uint32_t a0, uint32_t a1, uint32_t a2, uint32_t a3,
                                         uint32_t b0, uint32_t b1) {
    asm volatile(
        "mma.sync.aligned.m16n8k16.row.col.f32.bf16.bf16.f32 "
        "{%0,%1,%2,%3}, {%4,%5,%6,%7}, {%8,%9}, {%0,%1,%2,%3};"
        : "+f"(d0), "+f"(d1), "+f"(d2), "+f"(d3)
        : "r"(a0), "r"(a1), "r"(a2), "r"(a3), "r"(b0), "r"(b1));
}

// ---------------- shuffle-based block scan (NT threads, NT%32==0) ----------------
template <int NT, typename T>
__device__ __forceinline__ T bscan(T v, T& total) {
    __shared__ T ws[NT / 32];
    int t = threadIdx.x, lane = t & 31, w = t >> 5;
    __syncthreads();
    T x = v;
#pragma unroll
    for (int o = 1; o < 32; o <<= 1) {
        T y = __shfl_up_sync(0xffffffffu, x, o);
        if (lane >= o) x += y;
    }
    if (lane == 31) ws[w] = x;
    __syncthreads();
    if (t < NT / 32) {
        T s = ws[t];
#pragma unroll
        for (int o = 1; o < NT / 32; o <<= 1) {
            T y = __shfl_up_sync((NT / 32 < 32) ? ((1u << (NT / 32)) - 1u) : 0xffffffffu, s, o);
            if (t >= o) s += y;
        }
        ws[t] = s;
    }
    __syncthreads();
    T off = (w == 0) ? (T)0 : ws[w - 1];
    total = ws[NT / 32 - 1];
    return x + off;
}

// ---------------- fp32 -> bf16 hi/lo conversion of x ----------------
struct __align__(16) bf8 { __nv_bfloat16 v[8]; };
__global__ void convA_kernel(const float* __restrict__ x) {
    const long nch = (long)NN * (KP / 8);
    for (long id = (long)blockIdx.x * blockDim.x + threadIdx.x; id < nch;
         id += (long)gridDim.x * blockDim.x) {
        long row = id / (KP / 8);
        int c = (int)(id % (KP / 8));
        bf8 hi, lo;
        if (c < INF_ / 8) {
            const float* xp = x + row * INF_ + c * 8;
#pragma unroll
            for (int j = 0; j < 8; j++) {
                float v = xp[j];
                __nv_bfloat16 h = __float2bfloat16(v);
                hi.v[j] = h;
                lo.v[j] = __float2bfloat16(v - __bfloat162float(h));
            }
        } else {
#pragma unroll
            for (int j = 0; j < 8; j++) { hi.v[j] = __float2bfloat16(0.f); lo.v[j] = hi.v[j]; }
        }
        *reinterpret_cast<bf8*>(&g_Ahi[row * KP + c * 8]) = hi;
        *reinterpret_cast<bf8*>(&g_Alo[row * KP + c * 8]) = lo;
    }
}

__global__ void convBt_kernel(const float* __restrict__ W) {
    __shared__ float t[32][33];
    int kb = blockIdx.x * 32, nb = blockIdx.y * 32;
    int tx = threadIdx.x, ty = threadIdx.y;
#pragma unroll
    for (int r = 0; r < 32; r += 8) {
        int k = kb + ty + r, n = nb + tx;
        t[ty + r][tx] = (k < INF_) ? W[(long)k * D1 + n] : 0.f;
    }
    __syncthreads();
#pragma unroll
    for (int r = 0; r < 32; r += 8) {
        int n = nb + ty + r, k = kb + tx;
        float v = t[tx][ty + r];
        __nv_bfloat16 h = __float2bfloat16(v);
        g_Bhi[(long)n * KP + k] = h;
        g_Blo[(long)n * KP + k] = __float2bfloat16(v - __bfloat162float(h));
    }
}

// Wc = [Wm | Ws] : [512][128]
__global__ void buildWc(const float* __restrict__ Wm, const float* __restrict__ Ws) {
    int i = blockIdx.x * 256 + threadIdx.x;
    if (i < D1 * 64) {
        int k = i >> 6, n = i & 63;
        g_Wc[k * 128 + n] = Wm[i];
        g_Wc[k * 128 + 64 + n] = Ws[i];
    }
}

// ---------------- Wa[k][j] = sum_c W1[k, head*128+c] * a[head][c], j = h (src) / 4+h (dst) ----------------
__global__ void __launch_bounds__(32) buildWa(const float* __restrict__ W1,
                                              const float* __restrict__ a1s,
                                              const float* __restrict__ a1d) {
    int k = blockIdx.x;
    int lane = threadIdx.x;
#pragma unroll
    for (int j = 0; j < 8; j++) {
        int head = j & 3;
        const float* av = (j < 4) ? a1s : a1d;
        float s = 0.f;
        for (int c = lane; c < C1; c += 32)
            s = fmaf(W1[(long)k * D1 + head * C1 + c], av[head * C1 + c], s);
#pragma unroll
        for (int o = 16; o > 0; o >>= 1) s += __shfl_xor_sync(0xffffffffu, s, o);
        if (lane == 0) g_Wa[k * 8 + j] = s;
    }
}

// ---------------- es1/ed1 = x @ Wa (rank-8 GEMV, fp32-exact) ----------------
__global__ void __launch_bounds__(256) esGemm(const float* __restrict__ x,
                                              float* __restrict__ es,
                                              float* __restrict__ ed) {
    __shared__ float sh[8][8];
    int n = blockIdx.x;
    int t = threadIdx.x, lane = t & 31, w = t >> 5;
    float acc[8];
#pragma unroll
    for (int j = 0; j < 8; j++) acc[j] = 0.f;
    const float* xp = x + (long)n * INF_;
    for (int k = t; k < INF_; k += 256) {
        float xv = xp[k];
        const float* wp = &g_Wa[k * 8];
#pragma unroll
        for (int j = 0; j < 8; j++) acc[j] = fmaf(xv, wp[j], acc[j]);
    }
#pragma unroll
    for (int o = 16; o > 0; o >>= 1)
#pragma unroll
        for (int j = 0; j < 8; j++) acc[j] += __shfl_xor_sync(0xffffffffu, acc[j], o);
    if (lane == 0)
#pragma unroll
        for (int j = 0; j < 8; j++) sh[w][j] = acc[j];
    __syncthreads();
    if (t < 8) {
        float s = 0.f;
#pragma unroll
        for (int w2 = 0; w2 < 8; w2++) s += sh[w2][t];
        if (t < 4) es[n * HH + t] = s;
        else       ed[n * HH + (t - 4)] = s;
    }
}

// ---------------- HMMA GEMM (h1 = x @ W1), 128x128 tile, 5-stage pipe ----------------
__global__ void __launch_bounds__(256) mma_gemm(float* __restrict__ Cout) {
    extern __shared__ char smem[];
    const int tid = threadIdx.x;
    const int wid = tid >> 5, lane = tid & 31;
    const int g = lane >> 2, tig = lane & 3;
    const int wm = (wid & 3) * 32;
    const int wn = (wid >> 2) * 64;
    const int head = blockIdx.x;
    const int bn = head * 128;
    const int bm = blockIdx.y * 128;
    uint32_t sb = smem_u32(smem);

    float acc[2][8][4];
#pragma unroll
    for (int i = 0; i < 2; i++)
#pragma unroll
        for (int j = 0; j < 8; j++)
#pragma unroll
            for (int q = 0; q < 4; q++) acc[i][j][q] = 0.f;

    auto load_stage = [&](int s) {
        uint32_t base = sb + (uint32_t)(s % NPIPE) * STG_B;
        long gk = (long)s * KST;
#pragma unroll
        for (int t = 0; t < 8; t++) {
            int id = tid + t * 256;
            int mat = id >> 9;
            int r = (id >> 2) & 127;
            int c16 = id & 3;
            uint32_t so = base + (uint32_t)mat * TILE_B + (uint32_t)(r * 80 + c16 * 16);
            const __nv_bfloat16* gp;
            if (mat == 0)      gp = &g_Ahi[(long)(bm + r) * KP + gk + c16 * 8];
            else if (mat == 1) gp = &g_Alo[(long)(bm + r) * KP + gk + c16 * 8];
            else if (mat == 2) gp = &g_Bhi[(long)(bn + r) * KP + gk + c16 * 8];
            else               gp = &g_Blo[(long)(bn + r) * KP + gk + c16 * 8];
            cp16(so, gp);
        }
        cp_commit();
    };

    load_stage(0);
    load_stage(1);
    load_stage(2);
    load_stage(3);

    for (int s = 0; s < NSTG; s++) {
        int pending_after = NSTG - 1 - s;
        if (pending_after >= 3)      cp_wait<3>();
        else if (pending_after == 2) cp_wait<2>();
        else if (pending_after == 1) cp_wait<1>();
        else                         cp_wait<0>();
        __syncthreads();
        const char* stg = smem + (s % NPIPE) * STG_B;
        const uint32_t* Ah = (const uint32_t*)(stg);
        const uint32_t* Al = (const uint32_t*)(stg + TILE_B);
        const uint32_t* Bh = (const uint32_t*)(stg + 2 * TILE_B);
        const uint32_t* Bl = (const uint32_t*)(stg + 3 * TILE_B);
#pragma unroll
        for (int ks = 0; ks < 2; ks++) {
            int kh = ks * 8;
            uint32_t ah[2][4], al[2][4], bh[8][2], bl[8][2];
#pragma unroll
            for (int tm = 0; tm < 2; tm++) {
                int r = wm + tm * 16 + g;
                ah[tm][0] = Ah[r * 20 + kh + tig];
                ah[tm][1] = Ah[(r + 8) * 20 + kh + tig];
                ah[tm][2] = Ah[r * 20 + kh + 4 + tig];
                ah[tm][3] = Ah[(r + 8) * 20 + kh + 4 + tig];
                al[tm][0] = Al[r * 20 + kh + tig];
                al[tm][1] = Al[(r + 8) * 20 + kh + tig];
                al[tm][2] = Al[r * 20 + kh + 4 + tig];
                al[tm][3] = Al[(r + 8) * 20 + kh + 4 + tig];
            }
#pragma unroll
            for (int tn = 0; tn < 8; tn++) {
                int n = wn + tn * 8 + g;
                bh[tn][0] = Bh[n * 20 + kh + tig];
                bh[tn][1] = Bh[n * 20 + kh + 4 + tig];
                bl[tn][0] = Bl[n * 20 + kh + tig];
                bl[tn][1] = Bl[n * 20 + kh + 4 + tig];
            }
#pragma unroll
            for (int tm = 0; tm < 2; tm++)
#pragma unroll
                for (int tn = 0; tn < 8; tn++) {
                    float* d = acc[tm][tn];
                    mma_bf16(d[0], d[1], d[2], d[3],
                             ah[tm][0], ah[tm][1], ah[tm][2], ah[tm][3],
                             bh[tn][0], bh[tn][1]);
                    mma_bf16(d[0], d[1], d[2], d[3],
                             ah[tm][0], ah[tm][1], ah[tm][2], ah[tm][3],
                             bl[tn][0], bl[tn][1]);
                    mma_bf16(d[0], d[1], d[2], d[3],
                             al[tm][0], al[tm][1], al[tm][2], al[tm][3],
                             bh[tn][0], bh[tn][1]);
                }
        }
        __syncthreads();
        if (s + 4 < NSTG) load_stage(s + 4);
    }

#pragma unroll
    for (int tm = 0; tm < 2; tm++)
#pragma unroll
        for (int tn = 0; tn < 8; tn++) {
            int r0 = bm + wm + tm * 16 + g;
            int c0 = bn + wn + tn * 8 + 2 * tig;
            float* d = acc[tm][tn];
            *reinterpret_cast<float2*>(&Cout[(long)r0 * D1 + c0]) = make_float2(d[0], d[1]);
            *reinterpret_cast<float2*>(&Cout[(long)(r0 + 8) * D1 + c0]) = make_float2(d[2], d[3]);
        }
}

// ---------------- fp32 GEMM 64x64 (Nn=128) with fused evals2 epilogue ----------------
__global__ void __launch_bounds__(128) gemm64e(const float* __restrict__ A,
                                               const float* __restrict__ B,
                                               float* __restrict__ C, int K,
                                               const float* __restrict__ ams,
                                               const float* __restrict__ amd,
                                               const float* __restrict__ ass,
                                               const float* __restrict__ asd,
                                               float* __restrict__ esm, float* __restrict__ edm,
                                               float* __restrict__ ess, float* __restrict__ eds) {
    const int Nn = 128;
    __shared__ float As[2][64][8];
    __shared__ float Bs[2][8][64];
    __shared__ float esb[64][4], edb[64][4];
    const int tid = threadIdx.x;
    const int bm = blockIdx.y * 64;
    const int bn = blockIdx.x * 64;
    const int arow = tid >> 1, acol = (tid & 1) * 4;
    const int brow = tid >> 4, bcol = (tid & 15) * 4;
    const int ty = (tid >> 4) * 8;
    const int tx = (tid & 15) * 4;

    const float* Ag = A + (long)(bm + arow) * K + acol;
    const float* Bg = B + (long)brow * Nn + bn + bcol;
    uint32_t aS[2] = { smem_u32(&As[0][arow][acol]), smem_u32(&As[1][arow][acol]) };
    uint32_t bS[2] = { smem_u32(&Bs[0][brow][bcol]), smem_u32(&Bs[1][brow][bcol]) };

    float acc[8][4];
#pragma unroll
    for (int i = 0; i < 8; i++)
#pragma unroll
        for (int j = 0; j < 4; j++) acc[i][j] = 0.f;

    cp16(aS[0], Ag);
    cp16(bS[0], Bg);
    cp_commit();

    int stage = 0;
    for (int k0 = 0; k0 < K; k0 += 8) {
        if (k0 + 8 < K) {
            cp16(aS[stage ^ 1], Ag + (k0 + 8));
            cp16(bS[stage ^ 1], Bg + (long)(k0 + 8) * Nn);
            cp_commit();
            cp_wait<1>();
        } else {
            cp_wait<0>();
        }
        __syncthreads();
#pragma unroll
        for (int kk = 0; kk < 8; kk++) {
            float4 b0 = *reinterpret_cast<const float4*>(&Bs[stage][kk][tx]);
            float ra[8];
#pragma unroll
            for (int i = 0; i < 8; i++) ra[i] = As[stage][ty + i][kk];
#pragma unroll
            for (int i = 0; i < 8; i++) {
                acc[i][0] = fmaf(ra[i], b0.x, acc[i][0]);
                acc[i][1] = fmaf(ra[i], b0.y, acc[i][1]);
                acc[i][2] = fmaf(ra[i], b0.z, acc[i][2]);
                acc[i][3] = fmaf(ra[i], b0.w, acc[i][3]);
            }
        }
        __syncthreads();
        stage ^= 1;
    }
#pragma unroll
    for (int i = 0; i < 8; i++) {
        float* cp = C + (long)(bm + ty + i) * Nn + bn + tx;
        *reinterpret_cast<float4*>(cp) = make_float4(acc[i][0], acc[i][1], acc[i][2], acc[i][3]);
    }

    // fused evals2 epilogue
    int half = bn >> 6;
    const float* avs = half ? ass : ams;
    const float* avd = half ? asd : amd;
    float* eso = half ? ess : esm;
    float* edo = half ? eds : edm;
    int headT = (tid & 15) >> 2;
    int cc = tx & 15;
    float pes[8], ped[8];
#pragma unroll
    for (int i = 0; i < 8; i++) {
        float s1 = 0.f, s2 = 0.f;
#pragma unroll
        for (int j = 0; j < 4; j++) {
            float av = avs[headT * LATD + cc + j];
            float dv = avd[headT * LATD + cc + j];
            s1 = fmaf(acc[i][j], av, s1);
            s2 = fmaf(acc[i][j], dv, s2);
        }
        pes[i] = s1;
        ped[i] = s2;
    }
#pragma unroll
    for (int off = 1; off <= 2; off <<= 1)
#pragma unroll
        for (int i = 0; i < 8; i++) {
            pes[i] += __shfl_xor_sync(0xffffffffu, pes[i], off);
            ped[i] += __shfl_xor_sync(0xffffffffu, ped[i], off);
        }
    if ((tid & 3) == 0) {
#pragma unroll
        for (int i = 0; i < 8; i++) {
            esb[ty + i][headT] = pes[i];
            edb[ty + i][headT] = ped[i];
        }
    }
    __syncthreads();
    for (int idx = tid; idx < 64 * 4; idx += 128) {
        int r = idx >> 2, h = idx & 3;
        eso[(bm + r) * HH + h] = esb[r][h];
        edo[(bm + r) * HH + h] = edb[r][h];
    }
}

// ---------------- CSR build ----------------
__global__ void csr_zero() {
    int i = blockIdx.x * blockDim.x + threadIdx.x;
    if (i < NN) g_cur[i] = 0;
}
__global__ void csr_count(const int* __restrict__ dst) {
    int e = blockIdx.x * blockDim.x + threadIdx.x;
    if (e < EE) atomicAdd(&g_cur[dst[e]], 1);
}
__global__ void csr_scan() {
    __shared__ int sh[1024];
    int t = threadIdx.x;
    int c[4]; int s = 0;
#pragma unroll
    for (int u = 0; u < 4; u++) { c[u] = g_cur[t * 4 + u] + 1; s += c[u]; }
    sh[t] = s;
    __syncthreads();
    for (int o = 1; o < 1024; o <<= 1) {
        int v = (t >= o) ? sh[t - o] : 0;
        __syncthreads();
        sh[t] += v;
        __syncthreads();
    }
    int base = sh[t] - s;
#pragma unroll
    for (int u = 0; u < 4; u++) {
        g_off[t * 4 + u] = base;
        g_cur[t * 4 + u] = base;
        base += c[u];
    }
    if (t == 1023) g_off[NN] = sh[1023];
}
__global__ void csr_scatter2(const int* __restrict__ src, const int* __restrict__ dst) {
    int e = blockIdx.x * blockDim.x + threadIdx.x;
    if (e < EE) {
        int p = atomicAdd(&g_cur[dst[e]], 1);
        g_srcs[p] = src[e];
    } else if (e < ETOT) {
        int n = e - EE;
        int p = atomicAdd(&g_cur[n], 1);
        g_srcs[p] = n;
    }
}

// ---------------- sparse GAT layer, C=128, concat ----------------
__global__ void spagg_concat(const float* __restrict__ es, const float* __restrict__ ed,
                             const float* __restrict__ h, const float* __restrict__ b,
                             float* __restrict__ out) {
    int dst = blockIdx.x;
    int head = threadIdx.x >> 5;
    int lane = threadIdx.x & 31;
    int beg = g_off[dst], end = g_off[dst + 1];
    float edv = ed[dst * HH + head];

    float m = -INFINITY;
    for (int e = beg + lane; e < end; e += 32)
        m = fmaxf(m, lrelu(es[g_srcs[e] * HH + head] + edv));
    for (int o = 16; o > 0; o >>= 1) m = fmaxf(m, __shfl_xor_sync(0xffffffffu, m, o));

    float den = 0.f;
    for (int e = beg + lane; e < end; e += 32)
        den += __expf(lrelu(es[g_srcs[e] * HH + head] + edv) - m);
    for (int o = 16; o > 0; o >>= 1) den += __shfl_xor_sync(0xffffffffu, den, o);
    float inv = 1.f / (den + 1e-16f);

    float a0 = 0.f, a1 = 0.f, a2 = 0.f, a3 = 0.f;
    for (int e = beg; e < end; e++) {
        int s = g_srcs[e];
        float w = __expf(lrelu(es[s * HH + head] + edv) - m) * inv;
        const float* hp = h + s * D1 + head * C1;
        a0 = fmaf(w, hp[lane], a0);
        a1 = fmaf(w, hp[lane + 32], a1);
        a2 = fmaf(w, hp[lane + 64], a2);
        a3 = fmaf(w, hp[lane + 96], a3);
    }
    float* op = out + dst * D1 + head * C1;
    const float* bp = b + head * C1;
    op[lane]      = a0 + bp[lane];
    op[lane + 32] = a1 + bp[lane + 32];
    op[lane + 64] = a2 + bp[lane + 64];
    op[lane + 96] = a3 + bp[lane + 96];
}

// ---------------- sparse GAT mean layers; 2 edges per iter ----------------
__global__ void spagg_mean2(const float* __restrict__ esm, const float* __restrict__ edm,
                            const float* __restrict__ ess, const float* __restrict__ eds,
                            const float* __restrict__ hs2,
                            const float* __restrict__ bm, const float* __restrict__ bs,
                            float* __restrict__ zm, float* __restrict__ zs) {
    int half = blockIdx.y;
    const float* es = half ? ess : esm;
    const float* ed = half ? eds : edm;
    const float* b  = half ? bs : bm;
    float* out      = half ? zs : zm;
    int dst = blockIdx.x * 4 + (threadIdx.x >> 5);
    int lane = threadIdx.x & 31;
    int sub = lane >> 4;
    int c = lane & 15;
    int beg = g_off[dst], end = g_off[dst + 1];
    float acc = 0.f;
    for (int head = 0; head < HH; head++) {
        float edv = ed[dst * HH + head];
        float m = -INFINITY;
        for (int e = beg + lane; e < end; e += 32)
            m = fmaxf(m, lrelu(es[g_srcs[e] * HH + head] + edv));
        for (int o = 16; o > 0; o >>= 1) m = fmaxf(m, __shfl_xor_sync(0xffffffffu, m, o));
        float den = 0.f;
        for (int e = beg + lane; e < end; e += 32)
            den += __expf(lrelu(es[g_srcs[e] * HH + head] + edv) - m);
        for (int o = 16; o > 0; o >>= 1) den += __shfl_xor_sync(0xffffffffu, den, o);
        float inv = 1.f / (den + 1e-16f);
        for (int e = beg; e < end; e += 2) {
            int ee = e + sub;
            if (ee < end) {
                int s = g_srcs[ee];
                float w = __expf(lrelu(es[s * HH + head] + edv) - m) * inv;
                acc = fmaf(w, hs2[s * 128 + half * 64 + head * LATD + c], acc);
            }
        }
    }
    acc += __shfl_down_sync(0xffffffffu, acc, 16);
    if (lane < LATD) out[dst * LATD + lane] = acc * 0.25f + b[lane];
}

// ---------------- fused radix sort + weights + scalar scans ----------------
__device__ __forceinline__ float unmap_key(uint32_t kk) {
    uint32_t m = ~kk;
    return __uint_as_float((m & 0x80000000u) ? (m ^ 0x80000000u) : ~m);
}

__global__ void __launch_bounds__(1024) sortF(const float* __restrict__ esA,
                                              const float* __restrict__ esB) {
    extern __shared__ uint32_t sm[];
    uint32_t* KA = sm;
    uint32_t* VA = sm + 4096;
    uint32_t* KB = sm + 8192;
    uint32_t* VB = sm + 12288;
    uint32_t* WH = sm + 16384;

    int slot = blockIdx.x;
    int t = threadIdx.x;
    int w = t >> 5, lane = t & 31;
    const float* es = (slot < 4) ? esA : esB;
    int head = slot & 3;

    for (int i = t; i < NN; i += 1024) {
        uint32_t b = __float_as_uint(es[i * HH + head]);
        uint32_t m = (b & 0x80000000u) ? ~b : (b | 0x80000000u);
        KA[i] = ~m;
        VA[i] = (uint32_t)i;
    }
    __syncthreads();

    uint32_t *KI = KA, *VI = VA, *KO = KB, *VO = VB;

#pragma unroll
    for (int pass = 0; pass < 4; pass++) {
        int shift = pass * 8;
        for (int i = t; i < 32 * 257; i += 1024) WH[i] = 0;
        __syncthreads();

        uint32_t k_[4], v_[4], d_[4], lr_[4];
#pragma unroll
        for (int r = 0; r < 4; r++) {
            int idx = w * 128 + r * 32 + lane;
            k_[r] = KI[idx];
            v_[r] = VI[idx];
            d_[r] = (k_[r] >> shift) & 255u;
            unsigned mask = __match_any_sync(0xffffffffu, d_[r]);
            int phys = w * 257 + (int)d_[r];
            uint32_t before = WH[phys];
            __syncwarp();
            lr_[r] = before + (uint32_t)__popc(mask & ((1u << lane) - 1u));
            int leader = __ffs((int)mask) - 1;
            if (lane == leader) WH[phys] = before + (uint32_t)__popc(mask);
            __syncwarp();
        }
        __syncthreads();

        uint32_t loc[8], sum = 0;
        int dbase = t >> 2;
        int wbase = (t & 3) * 8;
#pragma unroll
        for (int u = 0; u < 8; u++) {
            loc[u] = WH[(wbase + u) * 257 + dbase];
            sum += loc[u];
        }
        uint32_t totU;
        uint32_t incl = bscan<1024, uint32_t>(sum, totU);
        uint32_t run = incl - sum;
        __syncthreads();
#pragma unroll
        for (int u = 0; u < 8; u++) {
            uint32_t c0 = loc[u];
            WH[(wbase + u) * 257 + dbase] = run;
            run += c0;
        }
        __syncthreads();

#pragma unroll
        for (int r = 0; r < 4; r++) {
            uint32_t dest = WH[w * 257 + (int)d_[r]] + lr_[r];
            KO[dest] = k_[r];
            VO[dest] = v_[r];
        }
        __syncthreads();
        uint32_t* tk = KI; KI = KO; KO = tk;
        uint32_t* tv = VI; VI = VO; VO = tv;
    }

    float mb = unmap_key(KI[0]);
    int base = t * 4;
    float w1v[4], w2v[4];
    float loc1 = 0.f, loc2 = 0.f;
#pragma unroll
    for (int u = 0; u < 4; u++) {
        int i = base + u;
        float kv = unmap_key(KI[i]);
        g_skey[slot * NN + i] = kv;
        g_perm[slot * NN + i] = (int)VI[i];
        float d = kv - mb;
        w1v[u] = __expf(d);
        w2v[u] = __expf(0.2f * d);
        g_w1s[slot * NN + i] = w1v[u];
        g_w2s[slot * NN + i] = w2v[u];
        loc1 += w1v[u];
        loc2 += w2v[u];
    }
    float tot1, tot2;
    float incl1 = bscan<1024, float>(loc1, tot1);
    float incl2 = bscan<1024, float>(loc2, tot2);
    float s = incl1 - loc1;
#pragma unroll
    for (int u = 0; u < 4; u++) { g_s1[slot * (NN + 1) + base + u] = s; s += w1v[u]; }
    if (t == 1023) g_s1[slot * (NN + 1) + NN] = tot1;
    float a2 = tot2 - incl2;
#pragma unroll
    for (int u = 3; u >= 0; u--) { a2 += w2v[u]; g_s2[slot * (NN + 1) + base + u] = a2; }
    if (t == 0) { g_s2[slot * (NN + 1) + NN] = 0.f; g_Mb[slot] = mb; }
}

// ---------------- fused gather + chunk-local scans ----------------
__global__ void __launch_bounds__(C1) vscanC(const float* __restrict__ h) {
    int head = blockIdx.x, ch = blockIdx.y, c = threadIdx.x;
    const int*   perm = g_perm + head * NN + ch * CHLC;
    const float* w1p  = g_w1s + head * NN + ch * CHLC;
    const float* w2p  = g_w2s + head * NN + ch * CHLC;
    long rowbase = (long)head * (NN + 1) + ch * CHLC;
    float hv[CHLC];
    float s = 0.f;
#pragma unroll
    for (int r = 0; r < CHLC; r++) {
        int p = perm[r];
        hv[r] = h[(p * HH + head) * C1 + c];
        s = fmaf(w1p[r], hv[r], s);
        g_P1[(rowbase + r + 1) * C1 + c] = s;
    }
    g_T1[(head * NCHC + ch) * C1 + c] = s;
    s = 0.f;
#pragma unroll
    for (int r = CHLC - 1; r >= 0; r--) {
        s = fmaf(w2p[r], hv[r], s);
        g_S2[(rowbase + r) * C1 + c] = s;
    }
    g_T2[(head * NCHC + ch) * C1 + c] = s;
}

__global__ void __launch_bounds__(128) vscanL(const float* __restrict__ hs2) {
    int slot = blockIdx.x;
    int grp = threadIdx.x >> 4;
    int c = threadIdx.x & 15;
    int ch = blockIdx.y * 8 + grp;
    int half = slot >> 2, head = slot & 3;
    const int*   perm = g_perm + slot * NN + ch * CHLL;
    const float* w1p  = g_w1s + slot * NN + ch * CHLL;
    const float* w2p  = g_w2s + slot * NN + ch * CHLL;
    long rowbase = (long)slot * (NN + 1) + ch * CHLL;
    float hv[CHLL];
    float s = 0.f;
#pragma unroll
    for (int r = 0; r < CHLL; r++) {
        int p = perm[r];
        hv[r] = hs2[p * 128 + half * 64 + head * LATD + c];
        s = fmaf(w1p[r], hv[r], s);
        g_P1[(rowbase + r + 1) * LATD + c] = s;
    }
    g_T1[(slot * NCHL + ch) * LATD + c] = s;
    s = 0.f;
#pragma unroll
    for (int r = CHLL - 1; r >= 0; r--) {
        s = fmaf(w2p[r], hv[r], s);
        g_S2[(rowbase + r) * LATD + c] = s;
    }
    g_T2[(slot * NCHL + ch) * LATD + c] = s;
}

// ---------------- chunk-total prefix/suffix (in place) ----------------
template <int C, int NCHX>
__global__ void tpre_kernel() {
    int slot = blockIdx.x, c = blockIdx.y, t = threadIdx.x;
    float v1 = g_T1[(slot * NCHX + t) * C + c];
    float v2 = g_T2[(slot * NCHX + t) * C + c];
    float tot1, tot2;
    float i1 = bscan<NCHX, float>(v1, tot1);
    float i2 = bscan<NCHX, float>(v2, tot2);
    g_T1[(slot * NCHX + t) * C + c] = i1 - v1;
    g_T2[(slot * NCHX + t) * C + c] = tot2 - i2;
}

__device__ __forceinline__ int bsearch_gt(const float* sk, float t) {
    int lo = 0, hi = NN;
    while (lo < hi) {
        int mid = (lo + hi) >> 1;
        if (sk[mid] > t) lo = mid + 1; else hi = mid;
    }
    return lo;
}

// ---------------- dense GAT layer, C=128, concat ----------------
__global__ void dense_concat(const float* __restrict__ ed, const float* __restrict__ b,
                             float* __restrict__ out) {
    int i = blockIdx.x;
    int head = blockIdx.y;
    int c = threadIdx.x;
    float a = ed[i * HH + head];
    int k = bsearch_gt(g_skey + head * NN, -a);
    float am = a + g_Mb[head];
    float A1 = __expf(am), A2 = __expf(0.2f * am);
    float s1k = g_s1[head * (NN + 1) + k];
    float s2k = g_s2[head * (NN + 1) + k];
    float den = A1 * s1k + A2 * s2k;
    float p1v = 0.f, s2v = 0.f;
    if (k > 0) {
        int q = (k - 1) / CHLC;
        p1v = g_T1[(head * NCHC + q) * C1 + c] + g_P1[((long)head * (NN + 1) + k) * C1 + c];
    }
    if (k < NN) {
        int q = k / CHLC;
        s2v = g_T2[(head * NCHC + q) * C1 + c] + g_S2[((long)head * (NN + 1) + k) * C1 + c];
    }
    float num = A1 * p1v + A2 * s2v;
    out[i * D1 + head * C1 + c] = num / den + b[head * C1 + c];
}

// ---------------- dense GAT mean layers, both halves in one launch ----------------
__global__ void dense_mean2(const float* __restrict__ edm, const float* __restrict__ eds,
                            const float* __restrict__ bm, const float* __restrict__ bs,
                            float* __restrict__ zm, float* __restrict__ zs) {
    __shared__ float sh[64];
    int i = blockIdx.x;
    int half = blockIdx.y;
    int t = threadIdx.x;
    int head = t >> 4;
    int c = t & 15;
    int slot = half * 4 + head;
    const float* ed = half ? eds : edm;
    float a = ed[i * HH + head];
    int k = bsearch_gt(g_skey + slot * NN, -a);
    float am = a + g_Mb[slot];
    float A1 = __expf(am), A2 = __expf(0.2f * am);
    float den = A1 * g_s1[slot * (NN + 1) + k] + A2 * g_s2[slot * (NN + 1) + k];
    float p1v = 0.f, s2v = 0.f;
    if (k > 0) {
        int q = (k - 1) / CHLL;
        p1v = g_T1[(slot * NCHL + q) * LATD + c] + g_P1[((long)slot * (NN + 1) + k) * LATD + c];
    }
    if (k < NN) {
        int q = k / CHLL;
        s2v = g_T2[(slot * NCHL + q) * LATD + c] + g_S2[((long)slot * (NN + 1) + k) * LATD + c];
    }
    float num = A1 * p1v + A2 * s2v;
    sh[t] = num / den;
    __syncthreads();
    if (t < LATD) {
        float* out = half ? zs : zm;
        const float* b = half ? bs : bm;
        out[i * LATD + t] = 0.25f * (sh[t] + sh[16 + t] + sh[32 + t] + sh[48 + t]) + b[t];
    }
}

// ---------------- launch ----------------
extern "C" void kernel_launch(void* const* d_in, const int* in_sizes, int n_in,
                              void* d_out, int out_size) {
    const float* x   = (const float*)d_in[0];
    const int*   ei  = (const int*)d_in[1];
    const float* W1  = (const float*)d_in[3];
    const float* a1s = (const float*)d_in[4];
    const float* a1d = (const float*)d_in[5];
    const float* b1  = (const float*)d_in[6];
    const float* Wm  = (const float*)d_in[7];
    const float* ams = (const float*)d_in[8];
    const float* amd = (const float*)d_in[9];
    const float* bm  = (const float*)d_in[10];
    const float* Ws  = (const float*)d_in[11];
    const float* ass = (const float*)d_in[12];
    const float* asd = (const float*)d_in[13];
    const float* bs  = (const float*)d_in[14];
    float* out = (float*)d_out;
    float* z1m = out;
    float* z1s = out + NN * LATD;
    float* z2m = out + 2 * NN * LATD;
    float* z2s = out + 3 * NN * LATD;

    const int* src = ei;
    const int* dst = ei + EE;

    float *h1, *x1, *x2, *hs2a, *hs2b, *Wc;
    float *es1, *ed1;
    float *es2am, *ed2am, *es2as, *ed2as, *es2bm, *ed2bm, *es2bs, *ed2bs;
    cudaGetSymbolAddress((void**)&h1,    g_h1);
    cudaGetSymbolAddress((void**)&x1,    g_x1);
    cudaGetSymbolAddress((void**)&x2,    g_x2);
    cudaGetSymbolAddress((void**)&hs2a,  g_hs2a);
    cudaGetSymbolAddress((void**)&hs2b,  g_hs2b);
    cudaGetSymbolAddress((void**)&Wc,    g_Wc);
    cudaGetSymbolAddress((void**)&es1,   g_es1);
    cudaGetSymbolAddress((void**)&ed1,   g_ed1);
    cudaGetSymbolAddress((void**)&es2am, g_es2am);
    cudaGetSymbolAddress((void**)&ed2am, g_ed2am);
    cudaGetSymbolAddress((void**)&es2as, g_es2as);
    cudaGetSymbolAddress((void**)&ed2as, g_ed2as);
    cudaGetSymbolAddress((void**)&es2bm, g_es2bm);
    cudaGetSymbolAddress((void**)&ed2bm, g_ed2bm);
    cudaGetSymbolAddress((void**)&es2bs, g_es2bs);
    cudaGetSymbolAddress((void**)&ed2bs, g_ed2bs);

    static cudaStream_t sA = nullptr, sB = nullptr;
    static cudaEvent_t ev0 = nullptr, evW = nullptr, evES = nullptr,
                       evMain = nullptr, evA = nullptr, evB = nullptr;
    if (sA == nullptr) {
        cudaStreamCreateWithFlags(&sA, cudaStreamNonBlocking);
        cudaStreamCreateWithFlags(&sB, cudaStreamNonBlocking);
        cudaEventCreateWithFlags(&ev0,    cudaEventDisableTiming);
        cudaEventCreateWithFlags(&evW,    cudaEventDisableTiming);
        cudaEventCreateWithFlags(&evES,   cudaEventDisableTiming);
        cudaEventCreateWithFlags(&evMain, cudaEventDisableTiming);
        cudaEventCreateWithFlags(&evA,    cudaEventDisableTiming);
        cudaEventCreateWithFlags(&evB,    cudaEventDisableTiming);
        cudaFuncSetAttribute(mma_gemm, cudaFuncAttributeMaxDynamicSharedMemorySize, NPIPE * STG_B);
        cudaFuncSetAttribute(sortF, cudaFuncAttributeMaxDynamicSharedMemorySize, SORT_SMEM_B);
    }

    // fork: CSR build (sA) + W-conversions/esGemm/sort (sB) overlap convA+mma (main)
    cudaEventRecord(ev0, 0);
    cudaStreamWaitEvent(sA, ev0, 0);
    cudaStreamWaitEvent(sB, ev0, 0);
    csr_zero<<<16, 256, 0, sA>>>();
    csr_count<<<(EE + 255) / 256, 256, 0, sA>>>(dst);
    csr_scan<<<1, 1024, 0, sA>>>();
    csr_scatter2<<<(ETOT + 255) / 256, 256, 0, sA>>>(src, dst);

    convBt_kernel<<<dim3(KP / 32, D1 / 32), dim3(32, 8), 0, sB>>>(W1);
    buildWc<<<(D1 * 64 + 255) / 256, 256, 0, sB>>>(Wm, Ws);
    cudaEventRecord(evW, sB);
    // es1/ed1 directly from x (rank-8 GEMV) + first sort — all overlap mma_gemm
    buildWa<<<INF_, 32, 0, sB>>>(W1, a1s, a1d);
    esGemm<<<NN, 256, 0, sB>>>(x, es1, ed1);
    cudaEventRecord(evES, sB);
    sortF<<<4, 1024, SORT_SMEM_B, sB>>>(es1, es1);

    convA_kernel<<<1024, 256>>>(x);
    cudaStreamWaitEvent(0, evW, 0);
    mma_gemm<<<dim3(HH, NN / 128), 256, NPIPE * STG_B>>>(h1);
    cudaEventRecord(evMain, 0);

    // ---- branch A (sparse) ----
    cudaStreamWaitEvent(sA, evMain, 0);
    cudaStreamWaitEvent(sA, evES, 0);
    spagg_concat<<<NN, 128, 0, sA>>>(es1, ed1, h1, b1, x1);
    gemm64e<<<dim3(2, NN / 64), 128, 0, sA>>>(x1, Wc, hs2a, D1,
                                              ams, amd, ass, asd,
                                              es2am, ed2am, es2as, ed2as);
    spagg_mean2<<<dim3(NN / 4, 2), 128, 0, sA>>>(es2am, ed2am, es2as, ed2as, hs2a,
                                                 bm, bs, z1m, z1s);
    cudaEventRecord(evA, sA);

    // ---- branch B (dense, rank-1 softmax); sortF already done on sB ----
    cudaStreamWaitEvent(sB, evMain, 0);
    vscanC<<<dim3(HH, NCHC), C1, 0, sB>>>(h1);
    tpre_kernel<C1, NCHC><<<dim3(HH, C1), NCHC, 0, sB>>>();
    dense_concat<<<dim3(NN, HH), C1, 0, sB>>>(ed1, b1, x2);
    gemm64e<<<dim3(2, NN / 64), 128, 0, sB>>>(x2, Wc, hs2b, D1,
                                              ams, amd, ass, asd,
                                              es2bm, ed2bm, es2bs, ed2bs);
    sortF<<<NSLOT, 1024, SORT_SMEM_B, sB>>>(es2bm, es2bs);
    vscanL<<<dim3(NSLOT, NCHL / 8), 128, 0, sB>>>(hs2b);
    tpre_kernel<LATD, NCHL><<<dim3(NSLOT, LATD), NCHL, 0, sB>>>();
    dense_mean2<<<dim3(NN, 2), 64, 0, sB>>>(ed2bm, ed2bs, bm, bs, z2m, z2s);
    cudaEventRecord(evB, sB);

    // join
    cudaStreamWaitEvent(0, evA, 0);
    cudaStreamWaitEvent(0, evB, 0);
}

// round 16
// speedup vs baseline: 1.0662x; 1.0662x over previous
#include <cuda_runtime.h>
#include <cuda_bf16.h>
#include <math.h>
#include <stdint.h>

#define NN   4096
#define EE   131072
#define INF_ 3000
#define HH   4
#define C1   128
#define D1   512   // H*C1
#define LATD 16
#define D2   64    // H*LATD
#define ETOT (EE + NN)
#define NCHC 128   // C1 scan chunks
#define CHLC 32    // C1 chunk length
#define NCHL 256   // LATD scan chunks
#define CHLL 16    // LATD chunk length
#define KP   3008  // padded K for MMA (94*32)
#define KST  32    // K per pipeline stage
#define NSTG (KP / KST)
#define ROWP 40    // padded smem row length in bf16 (32 + 8)
#define TILE_B (128 * ROWP * 2)
#define STG_B  (4 * TILE_B)
#define NPIPE 5    // pipeline stages
#define NSLOT 8    // sort slots (2 halves x 4 heads)
#define SORT_SMEM_U32 (4 * 4096 + 32 * 257)
#define SORT_SMEM_B   (SORT_SMEM_U32 * 4)

// ---------------- scratch (static device globals; no allocation) ----------------
__device__ float g_h1[NN * D1];
__device__ float g_x1[NN * D1];
__device__ float g_x2[NN * D1];
__device__ float g_hs2a[NN * 128];
__device__ float g_hs2b[NN * 128];
__device__ float g_Wc[D1 * 128];
__device__ float g_es1[NN * HH];
__device__ float g_ed1[NN * HH];
__device__ float g_es2am[NN * HH];
__device__ float g_ed2am[NN * HH];
__device__ float g_es2as[NN * HH];
__device__ float g_ed2as[NN * HH];
__device__ float g_es2bm[NN * HH];
__device__ float g_ed2bm[NN * HH];
__device__ float g_es2bs[NN * HH];
__device__ float g_ed2bs[NN * HH];
__device__ int   g_off[NN + 1];
__device__ int   g_cur[NN];
__device__ int   g_srcs[ETOT];
__device__ float g_skey[NSLOT * NN];
__device__ int   g_perm[NSLOT * NN];
__device__ float g_w1s[NSLOT * NN];
__device__ float g_w2s[NSLOT * NN];
__device__ float g_Mb[NSLOT];
__device__ float g_s1[NSLOT * (NN + 1)];
__device__ float g_s2[NSLOT * (NN + 1)];
__device__ float g_P1[HH * (NN + 1) * C1];
__device__ float g_S2[HH * (NN + 1) * C1];
__device__ float g_T1[65536];
__device__ float g_T2[65536];
// bf16 hi/lo split operands for HMMA GEMM
__device__ __align__(256) __nv_bfloat16 g_Ahi[(long)NN * KP];
__device__ __align__(256) __nv_bfloat16 g_Alo[(long)NN * KP];
__device__ __align__(256) __nv_bfloat16 g_Bhi[(long)D1 * KP];
__device__ __align__(256) __nv_bfloat16 g_Blo[(long)D1 * KP];

__device__ __forceinline__ float lrelu(float v) { return v > 0.f ? v : 0.2f * v; }

// ---------------- PTX helpers ----------------
__device__ __forceinline__ uint32_t smem_u32(const void* p) {
    return (uint32_t)__cvta_generic_to_shared(p);
}
__device__ __forceinline__ void cp16(uint32_t s, const void* g) {
    asm volatile("cp.async.cg.shared.global [%0], [%1], 16;\n" :: "r"(s), "l"(g));
}
__device__ __forceinline__ void cp_commit() {
    asm volatile("cp.async.commit_group;\n" ::: "memory");
}
template <int W>
__device__ __forceinline__ void cp_wait() {
    asm volatile("cp.async.wait_group %0;\n" :: "n"(W) : "memory");
}

__device__ __forceinline__ void mma_bf16(float& d0, float& d1, float& d2, float& d3,
                                         uint32_t a0, uint32_t a1, uint32_t a2, uint32_t a3,
                                         uint32_t b0, uint32_t b1) {
    asm volatile(
        "mma.sync.aligned.m16n8k16.row.col.f32.bf16.bf16.f32 "
        "{%0,%1,%2,%3}, {%4,%5,%6,%7}, {%8,%9}, {%0,%1,%2,%3};"
        : "+f"(d0), "+f"(d1), "+f"(d2), "+f"(d3)
        : "r"(a0), "r"(a1), "r"(a2), "r"(a3), "r"(b0), "r"(b1));
}

// ---------------- shuffle-based block scan (NT threads, NT%32==0) ----------------
template <int NT, typename T>
__device__ __forceinline__ T bscan(T v, T& total) {
    __shared__ T ws[NT / 32];
    int t = threadIdx.x, lane = t & 31, w = t >> 5;
    __syncthreads();
    T x = v;
#pragma unroll
    for (int o = 1; o < 32; o <<= 1) {
        T y = __shfl_up_sync(0xffffffffu, x, o);
        if (lane >= o) x += y;
    }
    if (lane == 31) ws[w] = x;
    __syncthreads();
    if (t < NT / 32) {
        T s = ws[t];
#pragma unroll
        for (int o = 1; o < NT / 32; o <<= 1) {
            T y = __shfl_up_sync((NT / 32 < 32) ? ((1u << (NT / 32)) - 1u) : 0xffffffffu, s, o);
            if (t >= o) s += y;
        }
        ws[t] = s;
    }
    __syncthreads();
    T off = (w == 0) ? (T)0 : ws[w - 1];
    total = ws[NT / 32 - 1];
    return x + off;
}

// ---------------- fp32 -> bf16 hi/lo conversion of x ----------------
struct __align__(16) bf8 { __nv_bfloat16 v[8]; };
__global__ void convA_kernel(const float* __restrict__ x) {
    const long nch = (long)NN * (KP / 8);
    for (long id = (long)blockIdx.x * blockDim.x + threadIdx.x; id < nch;
         id += (long)gridDim.x * blockDim.x) {
        long row = id / (KP / 8);
        int c = (int)(id % (KP / 8));
        bf8 hi, lo;
        if (c < INF_ / 8) {
            const float* xp = x + row * INF_ + c * 8;
#pragma unroll
            for (int j = 0; j < 8; j++) {
                float v = xp[j];
                __nv_bfloat16 h = __float2bfloat16(v);
                hi.v[j] = h;
                lo.v[j] = __float2bfloat16(v - __bfloat162float(h));
            }
        } else {
#pragma unroll
            for (int j = 0; j < 8; j++) { hi.v[j] = __float2bfloat16(0.f); lo.v[j] = hi.v[j]; }
        }
        *reinterpret_cast<bf8*>(&g_Ahi[row * KP + c * 8]) = hi;
        *reinterpret_cast<bf8*>(&g_Alo[row * KP + c * 8]) = lo;
    }
}

__global__ void convBt_kernel(const float* __restrict__ W) {
    __shared__ float t[32][33];
    int kb = blockIdx.x * 32, nb = blockIdx.y * 32;
    int tx = threadIdx.x, ty = threadIdx.y;
#pragma unroll
    for (int r = 0; r < 32; r += 8) {
        int k = kb + ty + r, n = nb + tx;
        t[ty + r][tx] = (k < INF_) ? W[(long)k * D1 + n] : 0.f;
    }
    __syncthreads();
#pragma unroll
    for (int r = 0; r < 32; r += 8) {
        int n = nb + ty + r, k = kb + tx;
        float v = t[tx][ty + r];
        __nv_bfloat16 h = __float2bfloat16(v);
        g_Bhi[(long)n * KP + k] = h;
        g_Blo[(long)n * KP + k] = __float2bfloat16(v - __bfloat162float(h));
    }
}

// Wc = [Wm | Ws] : [512][128]
__global__ void buildWc(const float* __restrict__ Wm, const float* __restrict__ Ws) {
    int i = blockIdx.x * 256 + threadIdx.x;
    if (i < D1 * 64) {
        int k = i >> 6, n = i & 63;
        g_Wc[k * 128 + n] = Wm[i];
        g_Wc[k * 128 + 64 + n] = Ws[i];
    }
}

// ---------------- HMMA GEMM (h1 = x @ W1) with fused layer-1 evals ----------------
__global__ void __launch_bounds__(256) mma_gemm(float* __restrict__ Cout,
                                                const float* __restrict__ asrc,
                                                const float* __restrict__ adst,
                                                float* __restrict__ es,
                                                float* __restrict__ ed) {
    extern __shared__ char smem[];
    const int tid = threadIdx.x;
    const int wid = tid >> 5, lane = tid & 31;
    const int g = lane >> 2, tig = lane & 3;
    const int wm = (wid & 3) * 32;
    const int wn = (wid >> 2) * 64;
    const int head = blockIdx.x;
    const int bn = head * 128;
    const int bm = blockIdx.y * 128;
    uint32_t sb = smem_u32(smem);

    float acc[2][8][4];
#pragma unroll
    for (int i = 0; i < 2; i++)
#pragma unroll
        for (int j = 0; j < 8; j++)
#pragma unroll
            for (int q = 0; q < 4; q++) acc[i][j][q] = 0.f;

    auto load_stage = [&](int s) {
        uint32_t base = sb + (uint32_t)(s % NPIPE) * STG_B;
        long gk = (long)s * KST;
#pragma unroll
        for (int t = 0; t < 8; t++) {
            int id = tid + t * 256;
            int mat = id >> 9;
            int r = (id >> 2) & 127;
            int c16 = id & 3;
            uint32_t so = base + (uint32_t)mat * TILE_B + (uint32_t)(r * 80 + c16 * 16);
            const __nv_bfloat16* gp;
            if (mat == 0)      gp = &g_Ahi[(long)(bm + r) * KP + gk + c16 * 8];
            else if (mat == 1) gp = &g_Alo[(long)(bm + r) * KP + gk + c16 * 8];
            else if (mat == 2) gp = &g_Bhi[(long)(bn + r) * KP + gk + c16 * 8];
            else               gp = &g_Blo[(long)(bn + r) * KP + gk + c16 * 8];
            cp16(so, gp);
        }
        cp_commit();
    };

    load_stage(0);
    load_stage(1);
    load_stage(2);
    load_stage(3);

    for (int s = 0; s < NSTG; s++) {
        int pending_after = NSTG - 1 - s;
        if (pending_after >= 3)      cp_wait<3>();
        else if (pending_after == 2) cp_wait<2>();
        else if (pending_after == 1) cp_wait<1>();
        else                         cp_wait<0>();
        __syncthreads();
        const char* stg = smem + (s % NPIPE) * STG_B;
        const uint32_t* Ah = (const uint32_t*)(stg);
        const uint32_t* Al = (const uint32_t*)(stg + TILE_B);
        const uint32_t* Bh = (const uint32_t*)(stg + 2 * TILE_B);
        const uint32_t* Bl = (const uint32_t*)(stg + 3 * TILE_B);
#pragma unroll
        for (int ks = 0; ks < 2; ks++) {
            int kh = ks * 8;
            uint32_t ah[2][4], al[2][4], bh[8][2], bl[8][2];
#pragma unroll
            for (int tm = 0; tm < 2; tm++) {
                int r = wm + tm * 16 + g;
                ah[tm][0] = Ah[r * 20 + kh + tig];
                ah[tm][1] = Ah[(r + 8) * 20 + kh + tig];
                ah[tm][2] = Ah[r * 20 + kh + 4 + tig];
                ah[tm][3] = Ah[(r + 8) * 20 + kh + 4 + tig];
                al[tm][0] = Al[r * 20 + kh + tig];
                al[tm][1] = Al[(r + 8) * 20 + kh + tig];
                al[tm][2] = Al[r * 20 + kh + 4 + tig];
                al[tm][3] = Al[(r + 8) * 20 + kh + 4 + tig];
            }
#pragma unroll
            for (int tn = 0; tn < 8; tn++) {
                int n = wn + tn * 8 + g;
                bh[tn][0] = Bh[n * 20 + kh + tig];
                bh[tn][1] = Bh[n * 20 + kh + 4 + tig];
                bl[tn][0] = Bl[n * 20 + kh + tig];
                bl[tn][1] = Bl[n * 20 + kh + 4 + tig];
            }
#pragma unroll
            for (int tm = 0; tm < 2; tm++)
#pragma unroll
                for (int tn = 0; tn < 8; tn++) {
                    float* d = acc[tm][tn];
                    mma_bf16(d[0], d[1], d[2], d[3],
                             ah[tm][0], ah[tm][1], ah[tm][2], ah[tm][3],
                             bh[tn][0], bh[tn][1]);
                    mma_bf16(d[0], d[1], d[2], d[3],
                             ah[tm][0], ah[tm][1], ah[tm][2], ah[tm][3],
                             bl[tn][0], bl[tn][1]);
                    mma_bf16(d[0], d[1], d[2], d[3],
                             al[tm][0], al[tm][1], al[tm][2], al[tm][3],
                             bh[tn][0], bh[tn][1]);
                }
        }
        __syncthreads();
        if (s + 4 < NSTG) load_stage(s + 4);
    }

    // write h1 tile
#pragma unroll
    for (int tm = 0; tm < 2; tm++)
#pragma unroll
        for (int tn = 0; tn < 8; tn++) {
            int r0 = bm + wm + tm * 16 + g;
            int c0 = bn + wn + tn * 8 + 2 * tig;
            float* d = acc[tm][tn];
            *reinterpret_cast<float2*>(&Cout[(long)r0 * D1 + c0]) = make_float2(d[0], d[1]);
            *reinterpret_cast<float2*>(&Cout[(long)(r0 + 8) * D1 + c0]) = make_float2(d[2], d[3]);
        }

    // fused evals epilogue: es/ed for this CTA's 128 rows, this head
    float* esbuf = (float*)smem;
    float* edbuf = esbuf + 128;
    if (tid < 128) { esbuf[tid] = 0.f; edbuf[tid] = 0.f; }
    __syncthreads();
    const float* asv = asrc + head * C1;
    const float* adv = adst + head * C1;
    float pes[2][2] = {{0.f, 0.f}, {0.f, 0.f}};
    float ped[2][2] = {{0.f, 0.f}, {0.f, 0.f}};
#pragma unroll
    for (int tm = 0; tm < 2; tm++)
#pragma unroll
        for (int tn = 0; tn < 8; tn++) {
            int c0 = wn + tn * 8 + 2 * tig;
            float a0s = asv[c0], a1s_ = asv[c0 + 1];
            float a0d = adv[c0], a1d_ = adv[c0 + 1];
            float* d = acc[tm][tn];
            pes[tm][0] = fmaf(d[0], a0s, fmaf(d[1], a1s_, pes[tm][0]));
            pes[tm][1] = fmaf(d[2], a0s, fmaf(d[3], a1s_, pes[tm][1]));
            ped[tm][0] = fmaf(d[0], a0d, fmaf(d[1], a1d_, ped[tm][0]));
            ped[tm][1] = fmaf(d[2], a0d, fmaf(d[3], a1d_, ped[tm][1]));
        }
#pragma unroll
    for (int off = 1; off <= 2; off <<= 1)
#pragma unroll
        for (int tm = 0; tm < 2; tm++)
#pragma unroll
            for (int q = 0; q < 2; q++) {
                pes[tm][q] += __shfl_xor_sync(0xffffffffu, pes[tm][q], off);
                ped[tm][q] += __shfl_xor_sync(0xffffffffu, ped[tm][q], off);
            }
    if (tig == 0) {
#pragma unroll
        for (int tm = 0; tm < 2; tm++) {
            int r0 = wm + tm * 16 + g;
            atomicAdd(&esbuf[r0], pes[tm][0]);
            atomicAdd(&esbuf[r0 + 8], pes[tm][1]);
            atomicAdd(&edbuf[r0], ped[tm][0]);
            atomicAdd(&edbuf[r0 + 8], ped[tm][1]);
        }
    }
    __syncthreads();
    if (tid < 128) {
        es[(bm + tid) * HH + head] = esbuf[tid];
        ed[(bm + tid) * HH + head] = edbuf[tid];
    }
}

// ---------------- fp32 GEMM 64x64 (Nn=128) with fused evals2 epilogue ----------------
__global__ void __launch_bounds__(128) gemm64e(const float* __restrict__ A,
                                               const float* __restrict__ B,
                                               float* __restrict__ C, int K,
                                               const float* __restrict__ ams,
                                               const float* __restrict__ amd,
                                               const float* __restrict__ ass,
                                               const float* __restrict__ asd,
                                               float* __restrict__ esm, float* __restrict__ edm,
                                               float* __restrict__ ess, float* __restrict__ eds) {
    const int Nn = 128;
    __shared__ float As[2][64][8];
    __shared__ float Bs[2][8][64];
    __shared__ float esb[64][4], edb[64][4];
    const int tid = threadIdx.x;
    const int bm = blockIdx.y * 64;
    const int bn = blockIdx.x * 64;
    const int arow = tid >> 1, acol = (tid & 1) * 4;
    const int brow = tid >> 4, bcol = (tid & 15) * 4;
    const int ty = (tid >> 4) * 8;
    const int tx = (tid & 15) * 4;

    const float* Ag = A + (long)(bm + arow) * K + acol;
    const float* Bg = B + (long)brow * Nn + bn + bcol;
    uint32_t aS[2] = { smem_u32(&As[0][arow][acol]), smem_u32(&As[1][arow][acol]) };
    uint32_t bS[2] = { smem_u32(&Bs[0][brow][bcol]), smem_u32(&Bs[1][brow][bcol]) };

    float acc[8][4];
#pragma unroll
    for (int i = 0; i < 8; i++)
#pragma unroll
        for (int j = 0; j < 4; j++) acc[i][j] = 0.f;

    cp16(aS[0], Ag);
    cp16(bS[0], Bg);
    cp_commit();

    int stage = 0;
    for (int k0 = 0; k0 < K; k0 += 8) {
        if (k0 + 8 < K) {
            cp16(aS[stage ^ 1], Ag + (k0 + 8));
            cp16(bS[stage ^ 1], Bg + (long)(k0 + 8) * Nn);
            cp_commit();
            cp_wait<1>();
        } else {
            cp_wait<0>();
        }
        __syncthreads();
#pragma unroll
        for (int kk = 0; kk < 8; kk++) {
            float4 b0 = *reinterpret_cast<const float4*>(&Bs[stage][kk][tx]);
            float ra[8];
#pragma unroll
            for (int i = 0; i < 8; i++) ra[i] = As[stage][ty + i][kk];
#pragma unroll
            for (int i = 0; i < 8; i++) {
                acc[i][0] = fmaf(ra[i], b0.x, acc[i][0]);
                acc[i][1] = fmaf(ra[i], b0.y, acc[i][1]);
                acc[i][2] = fmaf(ra[i], b0.z, acc[i][2]);
                acc[i][3] = fmaf(ra[i], b0.w, acc[i][3]);
            }
        }
        __syncthreads();
        stage ^= 1;
    }
#pragma unroll
    for (int i = 0; i < 8; i++) {
        float* cp = C + (long)(bm + ty + i) * Nn + bn + tx;
        *reinterpret_cast<float4*>(cp) = make_float4(acc[i][0], acc[i][1], acc[i][2], acc[i][3]);
    }

    // fused evals2 epilogue
    int half = bn >> 6;
    const float* avs = half ? ass : ams;
    const float* avd = half ? asd : amd;
    float* eso = half ? ess : esm;
    float* edo = half ? eds : edm;
    int headT = (tid & 15) >> 2;
    int cc = tx & 15;
    float pes[8], ped[8];
#pragma unroll
    for (int i = 0; i < 8; i++) {
        float s1 = 0.f, s2 = 0.f;
#pragma unroll
        for (int j = 0; j < 4; j++) {
            float av = avs[headT * LATD + cc + j];
            float dv = avd[headT * LATD + cc + j];
            s1 = fmaf(acc[i][j], av, s1);
            s2 = fmaf(acc[i][j], dv, s2);
        }
        pes[i] = s1;
        ped[i] = s2;
    }
#pragma unroll
    for (int off = 1; off <= 2; off <<= 1)
#pragma unroll
        for (int i = 0; i < 8; i++) {
            pes[i] += __shfl_xor_sync(0xffffffffu, pes[i], off);
            ped[i] += __shfl_xor_sync(0xffffffffu, ped[i], off);
        }
    if ((tid & 3) == 0) {
#pragma unroll
        for (int i = 0; i < 8; i++) {
            esb[ty + i][headT] = pes[i];
            edb[ty + i][headT] = ped[i];
        }
    }
    __syncthreads();
    for (int idx = tid; idx < 64 * 4; idx += 128) {
        int r = idx >> 2, h = idx & 3;
        eso[(bm + r) * HH + h] = esb[r][h];
        edo[(bm + r) * HH + h] = edb[r][h];
    }
}

// ---------------- CSR build ----------------
__global__ void csr_zero() {
    int i = blockIdx.x * blockDim.x + threadIdx.x;
    if (i < NN) g_cur[i] = 0;
}
__global__ void csr_count(const int* __restrict__ dst) {
    int e = blockIdx.x * blockDim.x + threadIdx.x;
    if (e < EE) atomicAdd(&g_cur[dst[e]], 1);
}
__global__ void csr_scan() {
    __shared__ int sh[1024];
    int t = threadIdx.x;
    int c[4]; int s = 0;
#pragma unroll
    for (int u = 0; u < 4; u++) { c[u] = g_cur[t * 4 + u] + 1; s += c[u]; }
    sh[t] = s;
    __syncthreads();
    for (int o = 1; o < 1024; o <<= 1) {
        int v = (t >= o) ? sh[t - o] : 0;
        __syncthreads();
        sh[t] += v;
        __syncthreads();
    }
    int base = sh[t] - s;
#pragma unroll
    for (int u = 0; u < 4; u++) {
        g_off[t * 4 + u] = base;
        g_cur[t * 4 + u] = base;
        base += c[u];
    }
    if (t == 1023) g_off[NN] = sh[1023];
}
__global__ void csr_scatter2(const int* __restrict__ src, const int* __restrict__ dst) {
    int e = blockIdx.x * blockDim.x + threadIdx.x;
    if (e < EE) {
        int p = atomicAdd(&g_cur[dst[e]], 1);
        g_srcs[p] = src[e];
    } else if (e < ETOT) {
        int n = e - EE;
        int p = atomicAdd(&g_cur[n], 1);
        g_srcs[p] = n;
    }
}

// ---------------- sparse GAT layer, C=128, concat ----------------
__global__ void spagg_concat(const float* __restrict__ es, const float* __restrict__ ed,
                             const float* __restrict__ h, const float* __restrict__ b,
                             float* __restrict__ out) {
    int dst = blockIdx.x;
    int head = threadIdx.x >> 5;
    int lane = threadIdx.x & 31;
    int beg = g_off[dst], end = g_off[dst + 1];
    float edv = ed[dst * HH + head];

    float m = -INFINITY;
    for (int e = beg + lane; e < end; e += 32)
        m = fmaxf(m, lrelu(es[g_srcs[e] * HH + head] + edv));
    for (int o = 16; o > 0; o >>= 1) m = fmaxf(m, __shfl_xor_sync(0xffffffffu, m, o));

    float den = 0.f;
    for (int e = beg + lane; e < end; e += 32)
        den += __expf(lrelu(es[g_srcs[e] * HH + head] + edv) - m);
    for (int o = 16; o > 0; o >>= 1) den += __shfl_xor_sync(0xffffffffu, den, o);
    float inv = 1.f / (den + 1e-16f);

    float a0 = 0.f, a1 = 0.f, a2 = 0.f, a3 = 0.f;
    for (int e = beg; e < end; e++) {
        int s = g_srcs[e];
        float w = __expf(lrelu(es[s * HH + head] + edv) - m) * inv;
        const float* hp = h + s * D1 + head * C1;
        a0 = fmaf(w, hp[lane], a0);
        a1 = fmaf(w, hp[lane + 32], a1);
        a2 = fmaf(w, hp[lane + 64], a2);
        a3 = fmaf(w, hp[lane + 96], a3);
    }
    float* op = out + dst * D1 + head * C1;
    const float* bp = b + head * C1;
    op[lane]      = a0 + bp[lane];
    op[lane + 32] = a1 + bp[lane + 32];
    op[lane + 64] = a2 + bp[lane + 64];
    op[lane + 96] = a3 + bp[lane + 96];
}

// ---------------- sparse GAT mean layers; 2 edges per iter ----------------
__global__ void spagg_mean2(const float* __restrict__ esm, const float* __restrict__ edm,
                            const float* __restrict__ ess, const float* __restrict__ eds,
                            const float* __restrict__ hs2,
                            const float* __restrict__ bm, const float* __restrict__ bs,
                            float* __restrict__ zm, float* __restrict__ zs) {
    int half = blockIdx.y;
    const float* es = half ? ess : esm;
    const float* ed = half ? eds : edm;
    const float* b  = half ? bs : bm;
    float* out      = half ? zs : zm;
    int dst = blockIdx.x * 4 + (threadIdx.x >> 5);
    int lane = threadIdx.x & 31;
    int sub = lane >> 4;
    int c = lane & 15;
    int beg = g_off[dst], end = g_off[dst + 1];
    float acc = 0.f;
    for (int head = 0; head < HH; head++) {
        float edv = ed[dst * HH + head];
        float m = -INFINITY;
        for (int e = beg + lane; e < end; e += 32)
            m = fmaxf(m, lrelu(es[g_srcs[e] * HH + head] + edv));
        for (int o = 16; o > 0; o >>= 1) m = fmaxf(m, __shfl_xor_sync(0xffffffffu, m, o));
        float den = 0.f;
        for (int e = beg + lane; e < end; e += 32)
            den += __expf(lrelu(es[g_srcs[e] * HH + head] + edv) - m);
        for (int o = 16; o > 0; o >>= 1) den += __shfl_xor_sync(0xffffffffu, den, o);
        float inv = 1.f / (den + 1e-16f);
        for (int e = beg; e < end; e += 2) {
            int ee = e + sub;
            if (ee < end) {
                int s = g_srcs[ee];
                float w = __expf(lrelu(es[s * HH + head] + edv) - m) * inv;
                acc = fmaf(w, hs2[s * 128 + half * 64 + head * LATD + c], acc);
            }
        }
    }
    acc += __shfl_down_sync(0xffffffffu, acc, 16);
    if (lane < LATD) out[dst * LATD + lane] = acc * 0.25f + b[lane];
}

// ---------------- fused radix sort + weights + scalar scans ----------------
__device__ __forceinline__ float unmap_key(uint32_t kk) {
    uint32_t m = ~kk;
    return __uint_as_float((m & 0x80000000u) ? (m ^ 0x80000000u) : ~m);
}

__global__ void __launch_bounds__(1024) sortF(const float* __restrict__ esA,
                                              const float* __restrict__ esB) {
    extern __shared__ uint32_t sm[];
    uint32_t* KA = sm;
    uint32_t* VA = sm + 4096;
    uint32_t* KB = sm + 8192;
    uint32_t* VB = sm + 12288;
    uint32_t* WH = sm + 16384;

    int slot = blockIdx.x;
    int t = threadIdx.x;
    int w = t >> 5, lane = t & 31;
    const float* es = (slot < 4) ? esA : esB;
    int head = slot & 3;

    for (int i = t; i < NN; i += 1024) {
        uint32_t b = __float_as_uint(es[i * HH + head]);
        uint32_t m = (b & 0x80000000u) ? ~b : (b | 0x80000000u);
        KA[i] = ~m;
        VA[i] = (uint32_t)i;
    }
    __syncthreads();

    uint32_t *KI = KA, *VI = VA, *KO = KB, *VO = VB;

#pragma unroll
    for (int pass = 0; pass < 4; pass++) {
        int shift = pass * 8;
        for (int i = t; i < 32 * 257; i += 1024) WH[i] = 0;
        __syncthreads();

        uint32_t k_[4], v_[4], d_[4], lr_[4];
#pragma unroll
        for (int r = 0; r < 4; r++) {
            int idx = w * 128 + r * 32 + lane;
            k_[r] = KI[idx];
            v_[r] = VI[idx];
            d_[r] = (k_[r] >> shift) & 255u;
            unsigned mask = __match_any_sync(0xffffffffu, d_[r]);
            int phys = w * 257 + (int)d_[r];
            uint32_t before = WH[phys];
            __syncwarp();
            lr_[r] = before + (uint32_t)__popc(mask & ((1u << lane) - 1u));
            int leader = __ffs((int)mask) - 1;
            if (lane == leader) WH[phys] = before + (uint32_t)__popc(mask);
            __syncwarp();
        }
        __syncthreads();

        uint32_t loc[8], sum = 0;
        int dbase = t >> 2;
        int wbase = (t & 3) * 8;
#pragma unroll
        for (int u = 0; u < 8; u++) {
            loc[u] = WH[(wbase + u) * 257 + dbase];
            sum += loc[u];
        }
        uint32_t totU;
        uint32_t incl = bscan<1024, uint32_t>(sum, totU);
        uint32_t run = incl - sum;
        __syncthreads();
#pragma unroll
        for (int u = 0; u < 8; u++) {
            uint32_t c0 = loc[u];
            WH[(wbase + u) * 257 + dbase] = run;
            run += c0;
        }
        __syncthreads();

#pragma unroll
        for (int r = 0; r < 4; r++) {
            uint32_t dest = WH[w * 257 + (int)d_[r]] + lr_[r];
            KO[dest] = k_[r];
            VO[dest] = v_[r];
        }
        __syncthreads();
        uint32_t* tk = KI; KI = KO; KO = tk;
        uint32_t* tv = VI; VI = VO; VO = tv;
    }

    float mb = unmap_key(KI[0]);
    int base = t * 4;
    float w1v[4], w2v[4];
    float loc1 = 0.f, loc2 = 0.f;
#pragma unroll
    for (int u = 0; u < 4; u++) {
        int i = base + u;
        float kv = unmap_key(KI[i]);
        g_skey[slot * NN + i] = kv;
        g_perm[slot * NN + i] = (int)VI[i];
        float d = kv - mb;
        w1v[u] = __expf(d);
        w2v[u] = __expf(0.2f * d);
        g_w1s[slot * NN + i] = w1v[u];
        g_w2s[slot * NN + i] = w2v[u];
        loc1 += w1v[u];
        loc2 += w2v[u];
    }
    float tot1, tot2;
    float incl1 = bscan<1024, float>(loc1, tot1);
    float incl2 = bscan<1024, float>(loc2, tot2);
    float s = incl1 - loc1;
#pragma unroll
    for (int u = 0; u < 4; u++) { g_s1[slot * (NN + 1) + base + u] = s; s += w1v[u]; }
    if (t == 1023) g_s1[slot * (NN + 1) + NN] = tot1;
    float a2 = tot2 - incl2;
#pragma unroll
    for (int u = 3; u >= 0; u--) { a2 += w2v[u]; g_s2[slot * (NN + 1) + base + u] = a2; }
    if (t == 0) { g_s2[slot * (NN + 1) + NN] = 0.f; g_Mb[slot] = mb; }
}

// ---------------- fused gather + chunk-local scans ----------------
__global__ void __launch_bounds__(C1) vscanC(const float* __restrict__ h) {
    int head = blockIdx.x, ch = blockIdx.y, c = threadIdx.x;
    const int*   perm = g_perm + head * NN + ch * CHLC;
    const float* w1p  = g_w1s + head * NN + ch * CHLC;
    const float* w2p  = g_w2s + head * NN + ch * CHLC;
    long rowbase = (long)head * (NN + 1) + ch * CHLC;
    float hv[CHLC];
    float s = 0.f;
#pragma unroll
    for (int r = 0; r < CHLC; r++) {
        int p = perm[r];
        hv[r] = h[(p * HH + head) * C1 + c];
        s = fmaf(w1p[r], hv[r], s);
        g_P1[(rowbase + r + 1) * C1 + c] = s;
    }
    g_T1[(head * NCHC + ch) * C1 + c] = s;
    s = 0.f;
#pragma unroll
    for (int r = CHLC - 1; r >= 0; r--) {
        s = fmaf(w2p[r], hv[r], s);
        g_S2[(rowbase + r) * C1 + c] = s;
    }
    g_T2[(head * NCHC + ch) * C1 + c] = s;
}

__global__ void __launch_bounds__(128) vscanL(const float* __restrict__ hs2) {
    int slot = blockIdx.x;
    int grp = threadIdx.x >> 4;
    int c = threadIdx.x & 15;
    int ch = blockIdx.y * 8 + grp;
    int half = slot >> 2, head = slot & 3;
    const int*   perm = g_perm + slot * NN + ch * CHLL;
    const float* w1p  = g_w1s + slot * NN + ch * CHLL;
    const float* w2p  = g_w2s + slot * NN + ch * CHLL;
    long rowbase = (long)slot * (NN + 1) + ch * CHLL;
    float hv[CHLL];
    float s = 0.f;
#pragma unroll
    for (int r = 0; r < CHLL; r++) {
        int p = perm[r];
        hv[r] = hs2[p * 128 + half * 64 + head * LATD + c];
        s = fmaf(w1p[r], hv[r], s);
        g_P1[(rowbase + r + 1) * LATD + c] = s;
    }
    g_T1[(slot * NCHL + ch) * LATD + c] = s;
    s = 0.f;
#pragma unroll
    for (int r = CHLL - 1; r >= 0; r--) {
        s = fmaf(w2p[r], hv[r], s);
        g_S2[(rowbase + r) * LATD + c] = s;
    }
    g_T2[(slot * NCHL + ch) * LATD + c] = s;
}

// ---------------- chunk-total prefix/suffix (in place) ----------------
template <int C, int NCHX>
__global__ void tpre_kernel() {
    int slot = blockIdx.x, c = blockIdx.y, t = threadIdx.x;
    float v1 = g_T1[(slot * NCHX + t) * C + c];
    float v2 = g_T2[(slot * NCHX + t) * C + c];
    float tot1, tot2;
    float i1 = bscan<NCHX, float>(v1, tot1);
    float i2 = bscan<NCHX, float>(v2, tot2);
    g_T1[(slot * NCHX + t) * C + c] = i1 - v1;
    g_T2[(slot * NCHX + t) * C + c] = tot2 - i2;
}

__device__ __forceinline__ int bsearch_gt(const float* sk, float t) {
    int lo = 0, hi = NN;
    while (lo < hi) {
        int mid = (lo + hi) >> 1;
        if (sk[mid] > t) lo = mid + 1; else hi = mid;
    }
    return lo;
}

// ---------------- dense GAT layer, C=128, concat ----------------
__global__ void dense_concat(const float* __restrict__ ed, const float* __restrict__ b,
                             float* __restrict__ out) {
    int i = blockIdx.x;
    int head = blockIdx.y;
    int c = threadIdx.x;
    float a = ed[i * HH + head];
    int k = bsearch_gt(g_skey + head * NN, -a);
    float am = a + g_Mb[head];
    float A1 = __expf(am), A2 = __expf(0.2f * am);
    float s1k = g_s1[head * (NN + 1) + k];
    float s2k = g_s2[head * (NN + 1) + k];
    float den = A1 * s1k + A2 * s2k;
    float p1v = 0.f, s2v = 0.f;
    if (k > 0) {
        int q = (k - 1) / CHLC;
        p1v = g_T1[(head * NCHC + q) * C1 + c] + g_P1[((long)head * (NN + 1) + k) * C1 + c];
    }
    if (k < NN) {
        int q = k / CHLC;
        s2v = g_T2[(head * NCHC + q) * C1 + c] + g_S2[((long)head * (NN + 1) + k) * C1 + c];
    }
    float num = A1 * p1v + A2 * s2v;
    out[i * D1 + head * C1 + c] = num / den + b[head * C1 + c];
}

// ---------------- dense GAT mean layers, both halves in one launch ----------------
__global__ void dense_mean2(const float* __restrict__ edm, const float* __restrict__ eds,
                            const float* __restrict__ bm, const float* __restrict__ bs,
                            float* __restrict__ zm, float* __restrict__ zs) {
    __shared__ float sh[64];
    int i = blockIdx.x;
    int half = blockIdx.y;
    int t = threadIdx.x;
    int head = t >> 4;
    int c = t & 15;
    int slot = half * 4 + head;
    const float* ed = half ? eds : edm;
    float a = ed[i * HH + head];
    int k = bsearch_gt(g_skey + slot * NN, -a);
    float am = a + g_Mb[slot];
    float A1 = __expf(am), A2 = __expf(0.2f * am);
    float den = A1 * g_s1[slot * (NN + 1) + k] + A2 * g_s2[slot * (NN + 1) + k];
    float p1v = 0.f, s2v = 0.f;
    if (k > 0) {
        int q = (k - 1) / CHLL;
        p1v = g_T1[(slot * NCHL + q) * LATD + c] + g_P1[((long)slot * (NN + 1) + k) * LATD + c];
    }
    if (k < NN) {
        int q = k / CHLL;
        s2v = g_T2[(slot * NCHL + q) * LATD + c] + g_S2[((long)slot * (NN + 1) + k) * LATD + c];
    }
    float num = A1 * p1v + A2 * s2v;
    sh[t] = num / den;
    __syncthreads();
    if (t < LATD) {
        float* out = half ? zs : zm;
        const float* b = half ? bs : bm;
        out[i * LATD + t] = 0.25f * (sh[t] + sh[16 + t] + sh[32 + t] + sh[48 + t]) + b[t];
    }
}

// ---------------- launch ----------------
extern "C" void kernel_launch(void* const* d_in, const int* in_sizes, int n_in,
                              void* d_out, int out_size) {
    const float* x   = (const float*)d_in[0];
    const int*   ei  = (const int*)d_in[1];
    const float* W1  = (const float*)d_in[3];
    const float* a1s = (const float*)d_in[4];
    const float* a1d = (const float*)d_in[5];
    const float* b1  = (const float*)d_in[6];
    const float* Wm  = (const float*)d_in[7];
    const float* ams = (const float*)d_in[8];
    const float* amd = (const float*)d_in[9];
    const float* bm  = (const float*)d_in[10];
    const float* Ws  = (const float*)d_in[11];
    const float* ass = (const float*)d_in[12];
    const float* asd = (const float*)d_in[13];
    const float* bs  = (const float*)d_in[14];
    float* out = (float*)d_out;
    float* z1m = out;
    float* z1s = out + NN * LATD;
    float* z2m = out + 2 * NN * LATD;
    float* z2s = out + 3 * NN * LATD;

    const int* src = ei;
    const int* dst = ei + EE;

    float *h1, *x1, *x2, *hs2a, *hs2b, *Wc;
    float *es1, *ed1;
    float *es2am, *ed2am, *es2as, *ed2as, *es2bm, *ed2bm, *es2bs, *ed2bs;
    cudaGetSymbolAddress((void**)&h1,    g_h1);
    cudaGetSymbolAddress((void**)&x1,    g_x1);
    cudaGetSymbolAddress((void**)&x2,    g_x2);
    cudaGetSymbolAddress((void**)&hs2a,  g_hs2a);
    cudaGetSymbolAddress((void**)&hs2b,  g_hs2b);
    cudaGetSymbolAddress((void**)&Wc,    g_Wc);
    cudaGetSymbolAddress((void**)&es1,   g_es1);
    cudaGetSymbolAddress((void**)&ed1,   g_ed1);
    cudaGetSymbolAddress((void**)&es2am, g_es2am);
    cudaGetSymbolAddress((void**)&ed2am, g_ed2am);
    cudaGetSymbolAddress((void**)&es2as, g_es2as);
    cudaGetSymbolAddress((void**)&ed2as, g_ed2as);
    cudaGetSymbolAddress((void**)&es2bm, g_es2bm);
    cudaGetSymbolAddress((void**)&ed2bm, g_ed2bm);
    cudaGetSymbolAddress((void**)&es2bs, g_es2bs);
    cudaGetSymbolAddress((void**)&ed2bs, g_ed2bs);

    static cudaStream_t sA = nullptr, sB = nullptr;
    static cudaEvent_t ev0 = nullptr, evW = nullptr, evMain = nullptr, evA = nullptr, evB = nullptr;
    if (sA == nullptr) {
        cudaStreamCreateWithFlags(&sA, cudaStreamNonBlocking);
        cudaStreamCreateWithFlags(&sB, cudaStreamNonBlocking);
        cudaEventCreateWithFlags(&ev0,    cudaEventDisableTiming);
        cudaEventCreateWithFlags(&evW,    cudaEventDisableTiming);
        cudaEventCreateWithFlags(&evMain, cudaEventDisableTiming);
        cudaEventCreateWithFlags(&evA,    cudaEventDisableTiming);
        cudaEventCreateWithFlags(&evB,    cudaEventDisableTiming);
        cudaFuncSetAttribute(mma_gemm, cudaFuncAttributeMaxDynamicSharedMemorySize, NPIPE * STG_B);
        cudaFuncSetAttribute(sortF, cudaFuncAttributeMaxDynamicSharedMemorySize, SORT_SMEM_B);
    }

    // fork: CSR build (sA) + W-side conversions (sB) overlap convA (main)
    cudaEventRecord(ev0, 0);
    cudaStreamWaitEvent(sA, ev0, 0);
    cudaStreamWaitEvent(sB, ev0, 0);
    csr_zero<<<16, 256, 0, sA>>>();
    csr_count<<<(EE + 255) / 256, 256, 0, sA>>>(dst);
    csr_scan<<<1, 1024, 0, sA>>>();
    csr_scatter2<<<(ETOT + 255) / 256, 256, 0, sA>>>(src, dst);

    convBt_kernel<<<dim3(KP / 32, D1 / 32), dim3(32, 8), 0, sB>>>(W1);
    buildWc<<<(D1 * 64 + 255) / 256, 256, 0, sB>>>(Wm, Ws);
    cudaEventRecord(evW, sB);

    convA_kernel<<<1024, 256>>>(x);
    cudaStreamWaitEvent(0, evW, 0);
    mma_gemm<<<dim3(HH, NN / 128), 256, NPIPE * STG_B>>>(h1, a1s, a1d, es1, ed1);
    cudaEventRecord(evMain, 0);

    // ---- branch A (sparse) ----
    cudaStreamWaitEvent(sA, evMain, 0);
    spagg_concat<<<NN, 128, 0, sA>>>(es1, ed1, h1, b1, x1);
    gemm64e<<<dim3(2, NN / 64), 128, 0, sA>>>(x1, Wc, hs2a, D1,
                                              ams, amd, ass, asd,
                                              es2am, ed2am, es2as, ed2as);
    spagg_mean2<<<dim3(NN / 4, 2), 128, 0, sA>>>(es2am, ed2am, es2as, ed2as, hs2a,
                                                 bm, bs, z1m, z1s);
    cudaEventRecord(evA, sA);

    // ---- branch B (dense, rank-1 softmax) ----
    cudaStreamWaitEvent(sB, evMain, 0);
    sortF<<<4, 1024, SORT_SMEM_B, sB>>>(es1, es1);
    vscanC<<<dim3(HH, NCHC), C1, 0, sB>>>(h1);
    tpre_kernel<C1, NCHC><<<dim3(HH, C1), NCHC, 0, sB>>>();
    dense_concat<<<dim3(NN, HH), C1, 0, sB>>>(ed1, b1, x2);
    gemm64e<<<dim3(2, NN / 64), 128, 0, sB>>>(x2, Wc, hs2b, D1,
                                              ams, amd, ass, asd,
                                              es2bm, ed2bm, es2bs, ed2bs);
    sortF<<<NSLOT, 1024, SORT_SMEM_B, sB>>>(es2bm, es2bs);
    vscanL<<<dim3(NSLOT, NCHL / 8), 128, 0, sB>>>(hs2b);
    tpre_kernel<LATD, NCHL><<<dim3(NSLOT, LATD), NCHL, 0, sB>>>();
    dense_mean2<<<dim3(NN, 2), 64, 0, sB>>>(ed2bm, ed2bs, bm, bs, z2m, z2s);
    cudaEventRecord(evB, sB);

    // join
    cudaStreamWaitEvent(0, evA, 0);
    cudaStreamWaitEvent(0, evB, 0);
}